// round 14
// baseline (speedup 1.0000x reference)
#include <cuda_runtime.h>
#include <math.h>
#include <stdint.h>

#define BB 256
#define TT 1024
#define MM 64
#define KH 512

#define RTHREADS 256
#define NCTA_R 128
#define GRP_CTAS 32

#define APITCH 68       // K=64 h-chunk pitch (68 % 32 == 4 -> conflict-free)
#define BPITCH 516      // W_hh row pitch    (516 % 32 == 4)
#define XPITCH 76       // x tile / W_ih pitch (76 % 32 == 12 -> conflict-free)
#define EPITCH 68

// float offsets into recurrence dynamic SMEM
#define OFF_WHH 0
#define OFF_WIH (64 * BPITCH)               // 33024
#define OFF_A0 (OFF_WIH + 64 * XPITCH)      // 37888
#define OFF_A1 (OFF_A0 + 64 * APITCH)       // 42240
#define OFF_AX (OFF_A1 + 64 * APITCH)       // 46592
#define OFF_BIAS (OFF_AX + 64 * XPITCH)     // 51456
#define SMEM_FLOATS (OFF_BIAS + 64)
#define SMEM_BYTES (SMEM_FLOATS * 4)        // 206080

__device__ float g_hs[(size_t)TT * BB * KH];
// tf32-converted, transposed, padded x: [grp][t][m=64][72]  (75.5 MB)
__device__ float g_xt[(size_t)4 * TT * 64 * 72];
// per-CTA progress flags, one 128B line each
__device__ unsigned g_flag[4][GRP_CTAS * 32];

__device__ __forceinline__ uint32_t f2tf32(float x) {
    uint32_t r;
    asm("cvt.rna.tf32.f32 %0, %1;" : "=r"(r) : "f"(x));
    return r;
}
__device__ __forceinline__ uint32_t smaddr(const void* p) {
    return (uint32_t)__cvta_generic_to_shared(p);
}
__device__ __forceinline__ unsigned ld_acq(const unsigned* p) {
    unsigned v;
    asm volatile("ld.acquire.gpu.global.u32 %0, [%1];" : "=r"(v) : "l"(p) : "memory");
    return v;
}
__device__ __forceinline__ void st_rel(unsigned* p, unsigned v) {
    asm volatile("st.release.gpu.global.u32 [%0], %1;" :: "l"(p), "r"(v) : "memory");
}

#define CP_COMMIT() asm volatile("cp.async.commit_group;" ::: "memory")
#define CP_WAIT0() asm volatile("cp.async.wait_group 0;" ::: "memory")
#define CP_WAIT1() asm volatile("cp.async.wait_group 1;" ::: "memory")

// warp-0 wait: flags of the 4 CTAs owning chunk g0/4 must reach tgt.
// Lanes read flag[(g0 + (lane&3))]; vote across the warp.
__device__ __forceinline__ void wait_flags4(const unsigned* flags, int g0,
                                            unsigned tgt, int lane) {
    const unsigned* fp = flags + (g0 + (lane & 3)) * 32;
    unsigned v;
    do {
        v = ld_acq(fp);
    } while (!__all_sync(0xFFFFFFFFu, (int)(v - tgt) >= 0));
}

// prefetch h chunk j (64 rows x 64 cols) from g_hs into Ab
__device__ __forceinline__ void prefetch_h(const float4* __restrict__ src,
                                           float* Ab, int j, int tid) {
#pragma unroll
    for (int i = 0; i < 4; i++) {
        int idx = tid + i * RTHREADS;       // < 1024
        int m = idx >> 4, q = idx & 15;
        uint32_t dst = smaddr(&Ab[m * APITCH + q * 4]);
        const float4* g = src + (size_t)m * (KH / 4) + j * 16 + q;
        asm volatile("cp.async.cg.shared.global [%0], [%1], 16;"
                     :: "r"(dst), "l"(g) : "memory");
    }
    CP_COMMIT();
}

// prefetch precomputed x tile (64 x 72 tf32, contiguous) into AX
__device__ __forceinline__ void prefetch_ax(const float4* __restrict__ src,
                                            float* AX, int tid) {
#pragma unroll
    for (int i = 0; i < 5; i++) {
        int idx = tid + i * RTHREADS;
        if (idx < 1152) {                  // 64 rows x 18 float4
            int m = idx / 18, q = idx - m * 18;
            uint32_t dst = smaddr(&AX[m * XPITCH + q * 4]);
            asm volatile("cp.async.cg.shared.global [%0], [%1], 16;"
                         :: "r"(dst), "l"(src + idx) : "memory");
        }
    }
    CP_COMMIT();
}

// K-step range [KS0,KS1) of a gate GEMM chunk. As: [64][AP] rows=M;
// Bk: [64][BP] rows=N. Warp tile 32x32; two k-half warp sets (split-K).
template <int KS0, int KS1, int AP, int BP>
__device__ __forceinline__ void compute_chunk(const float* __restrict__ As,
                                              const float* __restrict__ Bk,
                                              int m0w, int n0w, int gid, int tig,
                                              float (&d)[2][4][4]) {
#pragma unroll
    for (int ks = KS0; ks < KS1; ks++) {
        const int k0 = ks * 8;
        uint32_t a[2][4];
#pragma unroll
        for (int mt = 0; mt < 2; mt++) {
            const float* ap = As + (m0w + mt * 16 + gid) * AP + k0 + tig;
            a[mt][0] = __float_as_uint(ap[0]);
            a[mt][1] = __float_as_uint(ap[8 * AP]);
            a[mt][2] = __float_as_uint(ap[4]);
            a[mt][3] = __float_as_uint(ap[8 * AP + 4]);
        }
        uint32_t b[4][2];
#pragma unroll
        for (int nt = 0; nt < 4; nt++) {
            const float* bp = Bk + (n0w + nt * 8 + gid) * BP + k0 + tig;
            b[nt][0] = __float_as_uint(bp[0]);
            b[nt][1] = __float_as_uint(bp[4]);
        }
#pragma unroll
        for (int mt = 0; mt < 2; mt++)
#pragma unroll
            for (int nt = 0; nt < 4; nt++)
                asm volatile(
                    "mma.sync.aligned.m16n8k8.row.col.f32.tf32.tf32.f32 "
                    "{%0,%1,%2,%3}, {%4,%5,%6,%7}, {%8,%9}, {%0,%1,%2,%3};"
                    : "+f"(d[mt][nt][0]), "+f"(d[mt][nt][1]),
                      "+f"(d[mt][nt][2]), "+f"(d[mt][nt][3])
                    : "r"(a[mt][0]), "r"(a[mt][1]), "r"(a[mt][2]), "r"(a[mt][3]),
                      "r"(b[nt][0]), "r"(b[nt][1]));
    }
}

__device__ __forceinline__ float fast_sigmoid(float x) {
    return 1.0f / (1.0f + __expf(-x));
}
__device__ __forceinline__ float fast_tanh(float x) {
    x = fminf(fmaxf(x, -9.0f), 9.0f);
    float e2 = __expf(2.0f * x);
    return (e2 - 1.0f) / (e2 + 1.0f);
}

// ---------------------------------------------------------------------------
// x transpose/convert precompute: g_xt[grp][t][m][j] = tf32(x[grp*64+m, t, j])
// for j<65, 0 for 65<=j<72. grid (TT, 4), 128 threads.
// ---------------------------------------------------------------------------
__global__ void __launch_bounds__(128)
xt_kernel(const float* __restrict__ inputs) {
    const int t = blockIdx.x;
    const int grp = blockIdx.y;
    float* dst = g_xt + ((size_t)grp * TT + t) * (64 * 72);
    const float* src = inputs + (size_t)grp * 64 * (TT * 65) + (size_t)t * 65;
    for (int idx = threadIdx.x; idx < 64 * 72; idx += 128) {
        int m = idx / 72, j = idx - m * 72;
        float v = (j < 65) ? src[(size_t)m * (TT * 65) + j] : 0.0f;
        dst[idx] = __uint_as_float(f2tf32(v));
    }
}

// ---------------------------------------------------------------------------
// Persistent tf32 mma.sync LSTM recurrence. 8 warps (split-K 2x 2x2 grid).
// Fine-grained dependency: chunk j waits only on the flags of CTAs 4j..4j+3
// (the producers of hidden units [64j,64j+64)) -> barrier off the critical
// path; CTA skew pipelines across timesteps. Skew is safe: g_hs is a full
// per-t history and flags are monotonic.
// ---------------------------------------------------------------------------
__global__ void __launch_bounds__(RTHREADS, 1)
lstm_mma(const float* __restrict__ W_ih, const float* __restrict__ W_hh,
         const float* __restrict__ b_ih, const float* __restrict__ b_hh) {
    extern __shared__ __align__(16) float sm[];
    float* Whh = sm + OFF_WHH;
    float* Wih = sm + OFF_WIH;
    float* A0 = sm + OFF_A0;
    float* A1 = sm + OFF_A1;
    float* AX = sm + OFF_AX;
    float* sBias = sm + OFF_BIAS;

    const int tid = threadIdx.x;
    const int wid = tid >> 5;
    const int lane = tid & 31;
    const int gid = lane >> 2, tig = lane & 3;
    const int kh = wid >> 2;                 // k-half 0/1
    const int wq = wid & 3;
    const int m0w = (wq >> 1) * 32, n0w = (wq & 1) * 32;

    const int grp = blockIdx.x >> 5;
    const int hj = blockIdx.x & 31;
    const int batch_base = grp * 64;
    const int hid_base = hj * 16;

    const unsigned* flags = g_flag[grp];
    const float4* xt_base =
        (const float4*)(g_xt + (size_t)grp * TT * (64 * 72));

    // ---- one-time: weights (tf32-rounded) + bias ----
    for (int idx = tid; idx < 64 * BPITCH; idx += RTHREADS) {
        int r = idx / BPITCH, k = idx - r * BPITCH;
        int u = r >> 2, g = r & 3;
        int grow = g * KH + hid_base + u;
        Whh[idx] = (k < KH)
            ? __uint_as_float(f2tf32(W_hh[(size_t)grow * KH + k])) : 0.0f;
    }
    for (int idx = tid; idx < 64 * XPITCH; idx += RTHREADS) {
        int r = idx / XPITCH, k = idx - r * XPITCH;
        int u = r >> 2, g = r & 3;
        int grow = g * KH + hid_base + u;
        Wih[idx] = (k < 65)
            ? __uint_as_float(f2tf32(W_ih[(size_t)grow * 65 + k])) : 0.0f;
    }
    for (int idx = tid; idx < 64; idx += RTHREADS) {
        int u = idx >> 2, g = idx & 3;
        int grow = g * KH + hid_base + u;
        sBias[idx] = b_ih[grow] + b_hh[grow];
    }

    // prime AX(0)
    prefetch_ax(xt_base, AX, tid);
    __syncthreads();

    // Replay-safe flag base: own flag can't advance before our first release,
    // and all group flags are equal at launch (previous launch fully drained).
    unsigned base = 0;
    if (wid == 0) {
        if (lane == 0) base = ld_acq(&flags[hj * 32]);
        base = __shfl_sync(0xFFFFFFFFu, base, 0);
    }

    const int mcell = tid >> 2;          // epilogue: batch row
    const int qu = tid & 3;              // epilogue: unit quad
    float c_state[4];
#pragma unroll
    for (int i = 0; i < 4; i++) c_state[i] = 0.0f;

    for (int t = 0; t < TT; ++t) {
        float d[2][4][4];
#pragma unroll
        for (int mt = 0; mt < 2; mt++)
#pragma unroll
            for (int nt = 0; nt < 4; nt++)
#pragma unroll
                for (int i = 0; i < 4; i++) d[mt][nt][i] = 0.0f;

        if (t > 0) {
            const unsigned tgt = base + (unsigned)t;
            // chunk 0 needs only CTAs 0..3 of this group
            if (wid == 0) wait_flags4(flags, 0, tgt, lane);
            __syncthreads();

            const float4* src = (const float4*)(g_hs + (size_t)(t - 1) * BB * KH +
                                                (size_t)batch_base * KH);
            prefetch_h(src, A0, 0, tid);       // chunk0 (group after AX)
            CP_WAIT1();                        // AX(t) done; chunk0 in flight
            __syncthreads();

            // x GEMM (overlaps chunk0's cp.async flight)
            if (kh == 0)
                compute_chunk<0, 5, XPITCH, XPITCH>(AX, Wih, m0w, n0w, gid, tig, d);
            else
                compute_chunk<5, 9, XPITCH, XPITCH>(AX, Wih, m0w, n0w, gid, tig, d);

#pragma unroll 1
            for (int j = 0; j < 8; j++) {
                CP_WAIT0();
                if (j < 7 && wid == 0)
                    wait_flags4(flags, 4 * (j + 1), tgt, lane);
                __syncthreads();
                if (j < 7)
                    prefetch_h(src, (j & 1) ? A0 : A1, j + 1, tid);
                const float* Ab = (j & 1) ? A1 : A0;
                if (kh == 0)
                    compute_chunk<0, 4, APITCH, BPITCH>(Ab, Whh + j * 64, m0w,
                                                        n0w, gid, tig, d);
                else
                    compute_chunk<4, 8, APITCH, BPITCH>(Ab, Whh + j * 64, m0w,
                                                        n0w, gid, tig, d);
            }
        } else {
            CP_WAIT0();                        // AX(0)
            __syncthreads();
            if (kh == 0)
                compute_chunk<0, 5, XPITCH, XPITCH>(AX, Wih, m0w, n0w, gid, tig, d);
            else
                compute_chunk<5, 9, XPITCH, XPITCH>(AX, Wih, m0w, n0w, gid, tig, d);
        }
        __syncthreads();   // all warps done reading A0/A1 before Ep writes

        // ---- epilogue: k-half partials -> Ep0/Ep1 (=A0/A1) -> cell ----
        float* Ep = kh ? A1 : A0;
#pragma unroll
        for (int mt = 0; mt < 2; mt++)
#pragma unroll
            for (int nt = 0; nt < 4; nt++) {
                int rrow = m0w + mt * 16 + gid;
                int col = n0w + nt * 8 + tig * 2;
                Ep[rrow * EPITCH + col] = d[mt][nt][0];
                Ep[rrow * EPITCH + col + 1] = d[mt][nt][1];
                Ep[(rrow + 8) * EPITCH + col] = d[mt][nt][2];
                Ep[(rrow + 8) * EPITCH + col + 1] = d[mt][nt][3];
            }
        __syncthreads();

        {
            float* hdst = g_hs + (size_t)t * BB * KH +
                          (size_t)(batch_base + mcell) * KH + hid_base + qu * 4;
            float hv4[4];
#pragma unroll
            for (int i = 0; i < 4; i++) {
                int u = qu * 4 + i;
                float4 gA = *(const float4*)&A0[mcell * EPITCH + 4 * u];
                float4 gB = *(const float4*)&A1[mcell * EPITCH + 4 * u];
                float4 bb = *(const float4*)&sBias[4 * u];
                float iv = fast_sigmoid(gA.x + gB.x + bb.x);
                float fv = fast_sigmoid(gA.y + gB.y + bb.y);
                float gv = fast_tanh(gA.z + gB.z + bb.z);
                float ov = fast_sigmoid(gA.w + gB.w + bb.w);
                float cc = fv * c_state[i] + iv * gv;
                c_state[i] = cc;
                hv4[i] = __uint_as_float(f2tf32(ov * fast_tanh(cc)));
            }
            *(float4*)hdst = make_float4(hv4[0], hv4[1], hv4[2], hv4[3]);
        }
        __syncthreads();   // Ep reads + h stores done before release/refill

        if (tid == 0) {
            st_rel((unsigned*)&flags[hj * 32], base + (unsigned)t + 1u);
        }
        // AX(t+1): lands while we run ahead; first group next step
        if (t + 1 < TT)
            prefetch_ax(xt_base + (size_t)(t + 1) * (64 * 18), AX, tid);
    }
}

// ---------------------------------------------------------------------------
// Output projection: out[b,t,:] = hs[t,b,:] @ V_w^T + V_b
// ---------------------------------------------------------------------------
#define NTHREADS 256
#define PROJ_ROWS 64
#define PROJ_CHUNK 16
#define VPAD 68

__global__ void __launch_bounds__(NTHREADS, 1)
proj_kernel(const float* __restrict__ V_w, const float* __restrict__ V_b,
            float* __restrict__ out) {
    extern __shared__ __align__(16) float smemf[];
    float* sV = smemf;                    // [512][VPAD]
    float* sHr = sV + KH * VPAD;          // [16][512]
    float* sVb = sHr + PROJ_CHUNK * KH;   // [64]

    const int tid = threadIdx.x;
    const int mg = tid & 15;
    const int rs = tid >> 4;

    for (int idx = tid; idx < MM * KH; idx += NTHREADS) {
        int m = idx >> 9;
        int k = idx & 511;
        sV[k * VPAD + m] = V_w[idx];
    }
    for (int idx = tid; idx < MM; idx += NTHREADS) sVb[idx] = V_b[idx];
    __syncthreads();

    const int row_base = blockIdx.x * PROJ_ROWS;

    for (int ch = 0; ch < PROJ_ROWS; ch += PROJ_CHUNK) {
        const float4* src = (const float4*)(g_hs + (size_t)(row_base + ch) * KH);
        for (int idx = tid; idx < PROJ_CHUNK * (KH / 4); idx += NTHREADS) {
            ((float4*)sHr)[idx] = src[idx];
        }
        __syncthreads();

        float acc0 = sVb[mg * 4 + 0];
        float acc1 = sVb[mg * 4 + 1];
        float acc2 = sVb[mg * 4 + 2];
        float acc3 = sVb[mg * 4 + 3];
#pragma unroll 4
        for (int q = 0; q < KH / 4; q++) {
            float4 hv = *(const float4*)&sHr[rs * KH + q * 4];
            float4 v0 = *(const float4*)&sV[(q * 4 + 0) * VPAD + mg * 4];
            float4 v1 = *(const float4*)&sV[(q * 4 + 1) * VPAD + mg * 4];
            float4 v2 = *(const float4*)&sV[(q * 4 + 2) * VPAD + mg * 4];
            float4 v3 = *(const float4*)&sV[(q * 4 + 3) * VPAD + mg * 4];
            acc0 += hv.x * v0.x + hv.y * v1.x + hv.z * v2.x + hv.w * v3.x;
            acc1 += hv.x * v0.y + hv.y * v1.y + hv.z * v2.y + hv.w * v3.y;
            acc2 += hv.x * v0.z + hv.y * v1.z + hv.z * v2.z + hv.w * v3.z;
            acc3 += hv.x * v0.w + hv.y * v1.w + hv.z * v2.w + hv.w * v3.w;
        }

        int row = row_base + ch + rs;   // linear = t*B + b
        int t = row >> 8;
        int b = row & 255;
        float4 o = make_float4(acc0, acc1, acc2, acc3);
        *(float4*)&out[((size_t)b * TT + t) * MM + mg * 4] = o;
        __syncthreads();
    }
}

extern "C" void kernel_launch(void* const* d_in, const int* in_sizes, int n_in,
                              void* d_out, int out_size) {
    const float* inputs = (const float*)d_in[0];
    const float* W_ih   = (const float*)d_in[1];
    const float* W_hh   = (const float*)d_in[2];
    const float* b_ih   = (const float*)d_in[3];
    const float* b_hh   = (const float*)d_in[4];
    const float* V_w    = (const float*)d_in[5];
    const float* V_b    = (const float*)d_in[6];
    float* out = (float*)d_out;

    const int smem2 = (KH * VPAD + PROJ_CHUNK * KH + 64) * (int)sizeof(float);

    cudaFuncSetAttribute(lstm_mma, cudaFuncAttributeMaxDynamicSharedMemorySize,
                         SMEM_BYTES);
    cudaFuncSetAttribute(proj_kernel, cudaFuncAttributeMaxDynamicSharedMemorySize,
                         smem2);

    xt_kernel<<<dim3(TT, 4), 128>>>(inputs);
    lstm_mma<<<NCTA_R, RTHREADS, SMEM_BYTES>>>(W_ih, W_hh, b_ih, b_hh);
    proj_kernel<<<(BB * TT) / PROJ_ROWS, NTHREADS, smem2>>>(V_w, V_b, out);
}

// round 15
// speedup vs baseline: 1.2395x; 1.2395x over previous
#include <cuda_runtime.h>
#include <math.h>
#include <stdint.h>

#define BB 256
#define TT 1024
#define MM 64
#define KH 512

#define RTHREADS 288          // 8 compute warps + 1 sequencer warp
#define CTH 256               // compute threads
#define NCTA_R 128
#define GRP_CTAS 32

#define APITCH 72             // h/x operand pitch (72 % 32 == 8 -> conflict-free LDS.64)
#define BPITCH 520            // W_hh pitch (520 % 32 == 8)
#define EPITCH 68

// float offsets into dynamic SMEM
#define OFF_WHH 0
#define OFF_WIH (64 * BPITCH)                // 33280
#define OFF_A0 (OFF_WIH + 64 * APITCH)       // 37888
#define OFF_A1 (OFF_A0 + 64 * APITCH)        // 42496
#define OFF_AX (OFF_A1 + 64 * APITCH)        // 47104
#define OFF_BIAS (OFF_AX + 64 * APITCH)      // 51712
#define OFF_CTRL (OFF_BIAS + 64)             // 51776: [0]=sProg, [1]=sBase
#define SMEM_FLOATS (OFF_CTRL + 4)
#define SMEM_BYTES (SMEM_FLOATS * 4)         // 207120

__device__ float g_hs[(size_t)TT * BB * KH];           // k-pair-interleaved layout
__device__ float g_xt[(size_t)4 * TT * 64 * APITCH];   // permuted tf32 x tiles
__device__ unsigned g_flag[4][GRP_CTAS * 32];          // per-CTA flags, 128B apart

// k-pair interleave: pair (k, k+4) adjacent within each 8-group
__device__ __host__ __forceinline__ int kperm(int k) {
    return (k & ~7) + ((k & 3) << 1) + ((k >> 2) & 1);
}
__device__ __forceinline__ int kinv(int c) {
    int p = c & 7;
    return (c & ~7) + ((p & 1) << 2) + (p >> 1);
}

__device__ __forceinline__ uint32_t f2tf32(float x) {
    uint32_t r;
    asm("cvt.rna.tf32.f32 %0, %1;" : "=r"(r) : "f"(x));
    return r;
}
__device__ __forceinline__ uint32_t smaddr(const void* p) {
    return (uint32_t)__cvta_generic_to_shared(p);
}
__device__ __forceinline__ unsigned ld_acq(const unsigned* p) {
    unsigned v;
    asm volatile("ld.acquire.gpu.global.u32 %0, [%1];" : "=r"(v) : "l"(p) : "memory");
    return v;
}
__device__ __forceinline__ void st_rel(unsigned* p, unsigned v) {
    asm volatile("st.release.gpu.global.u32 [%0], %1;" :: "l"(p), "r"(v) : "memory");
}
__device__ __forceinline__ unsigned ld_acq_sh(uint32_t a) {
    unsigned v;
    asm volatile("ld.acquire.cta.shared.u32 %0, [%1];" : "=r"(v) : "r"(a) : "memory");
    return v;
}
__device__ __forceinline__ void st_rel_sh(uint32_t a, unsigned v) {
    asm volatile("st.release.cta.shared.u32 [%0], %1;" :: "r"(a), "r"(v) : "memory");
}

#define CP_COMMIT() asm volatile("cp.async.commit_group;" ::: "memory")
#define CP_WAIT0() asm volatile("cp.async.wait_group 0;" ::: "memory")
#define CP_WAIT1() asm volatile("cp.async.wait_group 1;" ::: "memory")
#define BAR1() asm volatile("bar.sync 1, 256;" ::: "memory")

// compute-warp gate: cheap SMEM acquire spin on the sequencer's progress
__device__ __forceinline__ void gate(uint32_t sProgA, unsigned target) {
    while ((int)(ld_acq_sh(sProgA) - target) < 0) {}
}

// prefetch h chunk j (64 rows x 64 cols, already permuted in g_hs) into Ab
__device__ __forceinline__ void prefetch_h(const float4* __restrict__ src,
                                           float* Ab, int j, int tid) {
#pragma unroll
    for (int i = 0; i < 4; i++) {
        int idx = tid + i * CTH;            // < 1024
        int m = idx >> 4, q = idx & 15;
        uint32_t dst = smaddr(&Ab[m * APITCH + q * 4]);
        const float4* g = src + (size_t)m * (KH / 4) + j * 16 + q;
        asm volatile("cp.async.cg.shared.global [%0], [%1], 16;"
                     :: "r"(dst), "l"(g) : "memory");
    }
    CP_COMMIT();
}

// prefetch x tile (64 x 72 permuted tf32, contiguous) into AX
__device__ __forceinline__ void prefetch_ax(const float4* __restrict__ src,
                                            float* AX, int tid) {
#pragma unroll
    for (int i = 0; i < 5; i++) {
        int idx = tid + i * CTH;
        if (idx < 1152) {                   // 64 rows x 18 float4
            int m = idx / 18, q = idx - m * 18;
            uint32_t dst = smaddr(&AX[m * APITCH + q * 4]);
            asm volatile("cp.async.cg.shared.global [%0], [%1], 16;"
                         :: "r"(dst), "l"(src + idx) : "memory");
        }
    }
    CP_COMMIT();
}

// K-step range [KS0,KS1). Operands stored k-pair-interleaved -> LDS.64 loads.
template <int KS0, int KS1, int AP, int BP>
__device__ __forceinline__ void compute_chunk(const float* __restrict__ As,
                                              const float* __restrict__ Bk,
                                              int m0w, int n0w, int gid, int tig,
                                              float (&d)[2][4][4]) {
#pragma unroll
    for (int ks = KS0; ks < KS1; ks++) {
        const int ko = ks * 8 + 2 * tig;
        uint32_t a[2][4];
#pragma unroll
        for (int mt = 0; mt < 2; mt++) {
            float2 lo = *(const float2*)&As[(m0w + mt * 16 + gid) * AP + ko];
            float2 hi = *(const float2*)&As[(m0w + mt * 16 + 8 + gid) * AP + ko];
            a[mt][0] = __float_as_uint(lo.x);
            a[mt][2] = __float_as_uint(lo.y);
            a[mt][1] = __float_as_uint(hi.x);
            a[mt][3] = __float_as_uint(hi.y);
        }
        uint32_t b[4][2];
#pragma unroll
        for (int nt = 0; nt < 4; nt++) {
            float2 bv = *(const float2*)&Bk[(n0w + nt * 8 + gid) * BP + ko];
            b[nt][0] = __float_as_uint(bv.x);
            b[nt][1] = __float_as_uint(bv.y);
        }
#pragma unroll
        for (int mt = 0; mt < 2; mt++)
#pragma unroll
            for (int nt = 0; nt < 4; nt++)
                asm volatile(
                    "mma.sync.aligned.m16n8k8.row.col.f32.tf32.tf32.f32 "
                    "{%0,%1,%2,%3}, {%4,%5,%6,%7}, {%8,%9}, {%0,%1,%2,%3};"
                    : "+f"(d[mt][nt][0]), "+f"(d[mt][nt][1]),
                      "+f"(d[mt][nt][2]), "+f"(d[mt][nt][3])
                    : "r"(a[mt][0]), "r"(a[mt][1]), "r"(a[mt][2]), "r"(a[mt][3]),
                      "r"(b[nt][0]), "r"(b[nt][1]));
    }
}

__device__ __forceinline__ float fast_sigmoid(float x) {
    return 1.0f / (1.0f + __expf(-x));
}
__device__ __forceinline__ float fast_tanh(float x) {
    x = fminf(fmaxf(x, -9.0f), 9.0f);
    float e2 = __expf(2.0f * x);
    return (e2 - 1.0f) / (e2 + 1.0f);
}

// ---------------------------------------------------------------------------
// x transpose/convert: g_xt[grp][t][m][c] = tf32(x[grp*64+m, t, kinv(c)])
// ---------------------------------------------------------------------------
__global__ void __launch_bounds__(128)
xt_kernel(const float* __restrict__ inputs) {
    const int t = blockIdx.x;
    const int grp = blockIdx.y;
    float* dst = g_xt + ((size_t)grp * TT + t) * (64 * APITCH);
    const float* src = inputs + (size_t)grp * 64 * (TT * 65) + (size_t)t * 65;
    for (int idx = threadIdx.x; idx < 64 * APITCH; idx += 128) {
        int m = idx / APITCH, c = idx - m * APITCH;
        int k = kinv(c);
        float v = (k < 65) ? src[(size_t)m * (TT * 65) + k] : 0.0f;
        dst[idx] = __uint_as_float(f2tf32(v));
    }
}

// ---------------------------------------------------------------------------
// Persistent tf32 mma.sync LSTM recurrence.
// Warps 0-7: split-K compute (named barrier 1). Warp 8: sequencer — polls the
// 32 group flags (one per lane), publishes per-chunk readiness to SMEM.
// Compute warps gate each chunk prefetch on a ~30cy LDS acquire spin.
// ---------------------------------------------------------------------------
__global__ void __launch_bounds__(RTHREADS, 1)
lstm_mma(const float* __restrict__ W_ih, const float* __restrict__ W_hh,
         const float* __restrict__ b_ih, const float* __restrict__ b_hh) {
    extern __shared__ __align__(16) float sm[];
    float* Whh = sm + OFF_WHH;
    float* Wih = sm + OFF_WIH;
    float* A0 = sm + OFF_A0;
    float* A1 = sm + OFF_A1;
    float* AX = sm + OFF_AX;
    float* sBias = sm + OFF_BIAS;
    unsigned* sCtrl = (unsigned*)(sm + OFF_CTRL);

    const int tid = threadIdx.x;
    const int lane = tid & 31;
    const int wid = tid >> 5;
    const int gid = lane >> 2, tig = lane & 3;
    const int kh = (wid >> 2) & 1;           // k-half for compute warps
    const int wq = wid & 3;
    const int m0w = (wq >> 1) * 32, n0w = (wq & 1) * 32;

    const int grp = blockIdx.x >> 5;
    const int hj = blockIdx.x & 31;
    const int batch_base = grp * 64;
    const int hid_base = hj * 16;

    unsigned* flags = (unsigned*)g_flag[grp];
    const float4* xt_base =
        (const float4*)(g_xt + (size_t)grp * TT * (64 * APITCH));
    const uint32_t sProgA = smaddr(&sCtrl[0]);

    // ---- one-time: weights (tf32, k-permuted) + bias; all 288 threads ----
    for (int idx = tid; idx < 64 * BPITCH; idx += RTHREADS) {
        int r = idx / BPITCH, c = idx - r * BPITCH;
        int k = kinv(c);
        int u = r >> 2, g = r & 3;
        int grow = g * KH + hid_base + u;
        Whh[idx] = (k < KH)
            ? __uint_as_float(f2tf32(W_hh[(size_t)grow * KH + k])) : 0.0f;
    }
    for (int idx = tid; idx < 64 * APITCH; idx += RTHREADS) {
        int r = idx / APITCH, c = idx - r * APITCH;
        int k = kinv(c);
        int u = r >> 2, g = r & 3;
        int grow = g * KH + hid_base + u;
        Wih[idx] = (k < 65)
            ? __uint_as_float(f2tf32(W_ih[(size_t)grow * 65 + k])) : 0.0f;
    }
    for (int idx = tid; idx < 64; idx += RTHREADS) {
        int u = idx >> 2, g = idx & 3;
        int grow = g * KH + hid_base + u;
        sBias[idx] = b_ih[grow] + b_hh[grow];
    }
    if (tid == 0) {
        sCtrl[0] = 8u;                          // sProg: below first target (9)
        sCtrl[1] = ld_acq(&flags[hj * 32]);     // replay-safe base (own flag)
    }
    if (tid < CTH) prefetch_ax(xt_base, AX, tid);   // prime AX(0)
    __syncthreads();    // the ONLY full-block barrier

    const unsigned base = sCtrl[1];

    // ================= sequencer warp =================
    if (tid >= CTH) {
        const unsigned* fp = (const unsigned*)flags + lane * 32;
        for (int t = 1; t < TT; t++) {
            const unsigned tgt = base + (unsigned)t;
            int j = 0;
            while (j < 8) {
                unsigned v = ld_acq(fp);
                unsigned m = __ballot_sync(0xFFFFFFFFu, (int)(v - tgt) >= 0);
                int nj = j;
                while (nj < 8 && ((m >> (4 * nj)) & 0xFu) == 0xFu) nj++;
                if (nj > j) {
                    j = nj;
                    if (lane == 0) st_rel_sh(sProgA, (unsigned)(t * 8 + j));
                }
            }
        }
        return;
    }

    // ================= compute warps =================
    const int mcell = tid >> 2;          // epilogue: batch row
    const int qu = tid & 3;              // epilogue: unit class
    float c_state[4];                    // units: qu, qu+4, 8+qu, 12+qu
#pragma unroll
    for (int i = 0; i < 4; i++) c_state[i] = 0.0f;

    for (int t = 0; t < TT; ++t) {
        float d[2][4][4];
#pragma unroll
        for (int mt = 0; mt < 2; mt++)
#pragma unroll
            for (int nt = 0; nt < 4; nt++)
#pragma unroll
                for (int i = 0; i < 4; i++) d[mt][nt][i] = 0.0f;

        if (t > 0) {
            const unsigned pt = (unsigned)(t * 8);
            gate(sProgA, pt + 1);        // chunk0 producers ready (LDS spin)

            const float4* src = (const float4*)(g_hs + (size_t)(t - 1) * BB * KH +
                                                (size_t)batch_base * KH);
            prefetch_h(src, A0, 0, tid);
            CP_WAIT1();                  // AX(t) arrived; chunk0 in flight
            BAR1();

            if (kh == 0)
                compute_chunk<0, 5, APITCH, APITCH>(AX, Wih, m0w, n0w, gid, tig, d);
            else
                compute_chunk<5, 9, APITCH, APITCH>(AX, Wih, m0w, n0w, gid, tig, d);

#pragma unroll 1
            for (int j = 0; j < 8; j++) {
                CP_WAIT0();
                BAR1();
                if (j < 7) {
                    gate(sProgA, pt + (unsigned)(j + 2));
                    prefetch_h(src, (j & 1) ? A0 : A1, j + 1, tid);
                }
                const float* Ab = (j & 1) ? A1 : A0;
                if (kh == 0)
                    compute_chunk<0, 4, APITCH, BPITCH>(Ab, Whh + j * 64, m0w,
                                                        n0w, gid, tig, d);
                else
                    compute_chunk<4, 8, APITCH, BPITCH>(Ab, Whh + j * 64, m0w,
                                                        n0w, gid, tig, d);
            }
        } else {
            CP_WAIT0();                  // AX(0)
            BAR1();
            if (kh == 0)
                compute_chunk<0, 5, APITCH, APITCH>(AX, Wih, m0w, n0w, gid, tig, d);
            else
                compute_chunk<5, 9, APITCH, APITCH>(AX, Wih, m0w, n0w, gid, tig, d);
        }
        BAR1();   // A bufs free for Ep

        // ---- epilogue: k-half partials -> Ep0/Ep1 (=A0/A1) ----
        float* Ep = kh ? A1 : A0;
#pragma unroll
        for (int mt = 0; mt < 2; mt++)
#pragma unroll
            for (int nt = 0; nt < 4; nt++) {
                int rrow = m0w + mt * 16 + gid;
                int col = n0w + nt * 8 + tig * 2;
                Ep[rrow * EPITCH + col] = d[mt][nt][0];
                Ep[rrow * EPITCH + col + 1] = d[mt][nt][1];
                Ep[(rrow + 8) * EPITCH + col] = d[mt][nt][2];
                Ep[(rrow + 8) * EPITCH + col + 1] = d[mt][nt][3];
            }
        BAR1();

        // ---- cell: units {qu, qu+4, 8+qu, 12+qu}; permuted float2 h store ----
        {
            float* hdst = g_hs + (size_t)t * BB * KH +
                          (size_t)(batch_base + mcell) * KH + hid_base;
            float hv[4];
#pragma unroll
            for (int i = 0; i < 4; i++) {
                int u = ((i & 1) << 2) + ((i >> 1) << 3) + qu;
                float4 gA = *(const float4*)&A0[mcell * EPITCH + 4 * u];
                float4 gB = *(const float4*)&A1[mcell * EPITCH + 4 * u];
                float4 bb = *(const float4*)&sBias[4 * u];
                float iv = fast_sigmoid(gA.x + gB.x + bb.x);
                float fv = fast_sigmoid(gA.y + gB.y + bb.y);
                float gv = fast_tanh(gA.z + gB.z + bb.z);
                float ov = fast_sigmoid(gA.w + gB.w + bb.w);
                float cc = fv * c_state[i] + iv * gv;
                c_state[i] = cc;
                hv[i] = __uint_as_float(f2tf32(ov * fast_tanh(cc)));
            }
            // pair (u, u+4) -> storage (2u', 2u'+1) within each 8-group
            *(float2*)(hdst + 2 * qu) = make_float2(hv[0], hv[1]);
            *(float2*)(hdst + 8 + 2 * qu) = make_float2(hv[2], hv[3]);
        }
        BAR1();   // Ep reads + h stores done before release / AX refill

        if (tid == 0) {
            st_rel(&flags[hj * 32], base + (unsigned)t + 1u);
        }
        if (t + 1 < TT)
            prefetch_ax(xt_base + (size_t)(t + 1) * (64 * APITCH / 4), AX, tid);
    }
}

// ---------------------------------------------------------------------------
// Output projection: out[b,t,:] = hs[t,b,:] @ V_w^T + V_b
// (h rows are k-permuted; V_w rows permuted identically at load -> identity)
// ---------------------------------------------------------------------------
#define NTHREADS 256
#define PROJ_ROWS 64
#define PROJ_CHUNK 16
#define VPAD 68

__global__ void __launch_bounds__(NTHREADS, 1)
proj_kernel(const float* __restrict__ V_w, const float* __restrict__ V_b,
            float* __restrict__ out) {
    extern __shared__ __align__(16) float smemf[];
    float* sV = smemf;                    // [512][VPAD], rows = permuted k
    float* sHr = sV + KH * VPAD;          // [16][512]
    float* sVb = sHr + PROJ_CHUNK * KH;   // [64]

    const int tid = threadIdx.x;
    const int mg = tid & 15;
    const int rs = tid >> 4;

    for (int idx = tid; idx < MM * KH; idx += NTHREADS) {
        int m = idx >> 9;
        int k = idx & 511;
        sV[kperm(k) * VPAD + m] = V_w[idx];
    }
    for (int idx = tid; idx < MM; idx += NTHREADS) sVb[idx] = V_b[idx];
    __syncthreads();

    const int row_base = blockIdx.x * PROJ_ROWS;

    for (int ch = 0; ch < PROJ_ROWS; ch += PROJ_CHUNK) {
        const float4* src = (const float4*)(g_hs + (size_t)(row_base + ch) * KH);
        for (int idx = tid; idx < PROJ_CHUNK * (KH / 4); idx += NTHREADS) {
            ((float4*)sHr)[idx] = src[idx];
        }
        __syncthreads();

        float acc0 = sVb[mg * 4 + 0];
        float acc1 = sVb[mg * 4 + 1];
        float acc2 = sVb[mg * 4 + 2];
        float acc3 = sVb[mg * 4 + 3];
#pragma unroll 4
        for (int q = 0; q < KH / 4; q++) {
            float4 hv = *(const float4*)&sHr[rs * KH + q * 4];
            float4 v0 = *(const float4*)&sV[(q * 4 + 0) * VPAD + mg * 4];
            float4 v1 = *(const float4*)&sV[(q * 4 + 1) * VPAD + mg * 4];
            float4 v2 = *(const float4*)&sV[(q * 4 + 2) * VPAD + mg * 4];
            float4 v3 = *(const float4*)&sV[(q * 4 + 3) * VPAD + mg * 4];
            acc0 += hv.x * v0.x + hv.y * v1.x + hv.z * v2.x + hv.w * v3.x;
            acc1 += hv.x * v0.y + hv.y * v1.y + hv.z * v2.y + hv.w * v3.y;
            acc2 += hv.x * v0.z + hv.y * v1.z + hv.z * v2.z + hv.w * v3.z;
            acc3 += hv.x * v0.w + hv.y * v1.w + hv.z * v2.w + hv.w * v3.w;
        }

        int row = row_base + ch + rs;   // linear = t*B + b
        int t = row >> 8;
        int b = row & 255;
        float4 o = make_float4(acc0, acc1, acc2, acc3);
        *(float4*)&out[((size_t)b * TT + t) * MM + mg * 4] = o;
        __syncthreads();
    }
}

extern "C" void kernel_launch(void* const* d_in, const int* in_sizes, int n_in,
                              void* d_out, int out_size) {
    const float* inputs = (const float*)d_in[0];
    const float* W_ih   = (const float*)d_in[1];
    const float* W_hh   = (const float*)d_in[2];
    const float* b_ih   = (const float*)d_in[3];
    const float* b_hh   = (const float*)d_in[4];
    const float* V_w    = (const float*)d_in[5];
    const float* V_b    = (const float*)d_in[6];
    float* out = (float*)d_out;

    const int smem2 = (KH * VPAD + PROJ_CHUNK * KH + 64) * (int)sizeof(float);

    cudaFuncSetAttribute(lstm_mma, cudaFuncAttributeMaxDynamicSharedMemorySize,
                         SMEM_BYTES);
    cudaFuncSetAttribute(proj_kernel, cudaFuncAttributeMaxDynamicSharedMemorySize,
                         smem2);

    xt_kernel<<<dim3(TT, 4), 128>>>(inputs);
    lstm_mma<<<NCTA_R, RTHREADS, SMEM_BYTES>>>(W_ih, W_hh, b_ih, b_hh);
    proj_kernel<<<(BB * TT) / PROJ_ROWS, NTHREADS, smem2>>>(V_w, V_b, out);
}

// round 16
// speedup vs baseline: 1.4281x; 1.1521x over previous
#include <cuda_runtime.h>
#include <cuda_fp16.h>
#include <math.h>
#include <stdint.h>

#define BB 256
#define TT 1024
#define MM 64
#define KH 512

#define RTHREADS 288          // 8 compute warps + 1 sequencer warp
#define CTH 256
#define NCTA_R 128
#define GRP_CTAS 32

#define APH 80                // A/X tile pitch in halves (160B: 16B-aligned, conflict-free)
#define BPH 524               // Whh pitch in halves (1048B: conflict-free)
#define XWPH 84               // Wih pitch in halves (168B: conflict-free)
#define EPITCH 68             // epilogue float pitch

// byte offsets into dynamic SMEM (all 16B aligned)
#define OFF_WHH 0
#define OFF_WIH (64 * BPH * 2)                 // 67072
#define OFF_A0 (OFF_WIH + 64 * XWPH * 2)       // 77824
#define OFF_A1 (OFF_A0 + 64 * APH * 2)         // 88064
#define OFF_AX (OFF_A1 + 64 * APH * 2)         // 98304
#define OFF_EP0 (OFF_AX + 64 * APH * 2)        // 108544
#define OFF_EP1 (OFF_EP0 + 64 * EPITCH * 4)    // 125952
#define OFF_BIAS (OFF_EP1 + 64 * EPITCH * 4)   // 143360
#define OFF_CTRL (OFF_BIAS + 64 * 4)           // 143616
#define SMEM_BYTES (OFF_CTRL + 16)             // 143632

__device__ __half g_hs[(size_t)TT * BB * KH];          // k16-permuted fp16 h history (268MB)
__device__ __half g_xt[(size_t)4 * TT * 64 * APH];     // permuted fp16 x tiles (42MB)
__device__ unsigned g_flag[4][GRP_CTAS * 32];          // per-CTA flags, 128B apart

// k16 permutation: within each 16-group, order [0,1,8,9, 2,3,10,11, 4,5,12,13, 6,7,14,15]
__device__ __host__ __forceinline__ int p16(int u) {
    return (u & 1) + (((u >> 3) & 1) << 1) + (((u >> 1) & 3) << 2);
}
__device__ __forceinline__ int kinv16(int c) {
    return (c & 1) + (((c >> 2) & 3) << 1) + (((c >> 1) & 1) << 3);
}

__device__ __forceinline__ uint32_t smaddr(const void* p) {
    return (uint32_t)__cvta_generic_to_shared(p);
}
__device__ __forceinline__ unsigned ld_acq(const unsigned* p) {
    unsigned v;
    asm volatile("ld.acquire.gpu.global.u32 %0, [%1];" : "=r"(v) : "l"(p) : "memory");
    return v;
}
__device__ __forceinline__ void st_rel(unsigned* p, unsigned v) {
    asm volatile("st.release.gpu.global.u32 [%0], %1;" :: "l"(p), "r"(v) : "memory");
}
__device__ __forceinline__ unsigned ld_acq_sh(uint32_t a) {
    unsigned v;
    asm volatile("ld.acquire.cta.shared.u32 %0, [%1];" : "=r"(v) : "r"(a) : "memory");
    return v;
}
__device__ __forceinline__ void st_rel_sh(uint32_t a, unsigned v) {
    asm volatile("st.release.cta.shared.u32 [%0], %1;" :: "r"(a), "r"(v) : "memory");
}

#define CP_COMMIT() asm volatile("cp.async.commit_group;" ::: "memory")
#define CP_WAIT0() asm volatile("cp.async.wait_group 0;" ::: "memory")
#define CP_WAIT1() asm volatile("cp.async.wait_group 1;" ::: "memory")
#define BAR1() asm volatile("bar.sync 1, 256;" ::: "memory")

__device__ __forceinline__ void gate(uint32_t sProgA, unsigned target) {
    while ((int)(ld_acq_sh(sProgA) - target) < 0) {}
}

// prefetch h chunk j (64 rows x 64 halves = 8KB) from g_hs into Ab (pitch APH)
__device__ __forceinline__ void prefetch_h(const __half* __restrict__ srcH,
                                           __half* Ab, int j, int tid) {
    const float4* src = (const float4*)srcH;   // row stride 512h = 64 float4
#pragma unroll
    for (int i = 0; i < 2; i++) {
        int idx = tid + i * CTH;               // < 512
        int m = idx >> 3, q = idx & 7;
        uint32_t dst = smaddr(Ab + m * APH + q * 8);
        const float4* g = src + (size_t)m * 64 + j * 8 + q;
        asm volatile("cp.async.cg.shared.global [%0], [%1], 16;"
                     :: "r"(dst), "l"(g) : "memory");
    }
    CP_COMMIT();
}

// prefetch x tile (64 x 80 halves contiguous = 10KB) into AX
__device__ __forceinline__ void prefetch_ax(const __half* __restrict__ srcH,
                                            __half* AX, int tid) {
    const float4* src = (const float4*)srcH;
#pragma unroll
    for (int i = 0; i < 3; i++) {
        int idx = tid + i * CTH;
        if (idx < 640) {                       // 64 rows x 10 float4
            int m = idx / 10, q = idx - m * 10;
            uint32_t dst = smaddr(AX + m * APH + q * 8);
            asm volatile("cp.async.cg.shared.global [%0], [%1], 16;"
                         :: "r"(dst), "l"(src + idx) : "memory");
        }
    }
    CP_COMMIT();
}

// fp16 m16n8k16 chunk: k16-steps [KS0,KS1). As rows=M, Bk rows=N, both
// k16-permuted -> each fragment is one LDS.64.
template <int KS0, int KS1, int APc, int BPc>
__device__ __forceinline__ void compute_chunk(const __half* __restrict__ As,
                                              const __half* __restrict__ Bk,
                                              int m0w, int n0w, int gid, int tig,
                                              float (&d)[2][4][4]) {
#pragma unroll
    for (int ks = KS0; ks < KS1; ks++) {
        const int ko = ks * 16 + 4 * tig;
        uint32_t a[2][4];
#pragma unroll
        for (int mt = 0; mt < 2; mt++) {
            uint2 lo = *(const uint2*)&As[(m0w + mt * 16 + gid) * APc + ko];
            uint2 hi = *(const uint2*)&As[(m0w + mt * 16 + 8 + gid) * APc + ko];
            a[mt][0] = lo.x;   // (row gid,   k 2t:2t+1)
            a[mt][1] = hi.x;   // (row gid+8, k 2t:2t+1)
            a[mt][2] = lo.y;   // (row gid,   k 2t+8:+9)
            a[mt][3] = hi.y;   // (row gid+8, k 2t+8:+9)
        }
        uint32_t b[4][2];
#pragma unroll
        for (int nt = 0; nt < 4; nt++) {
            uint2 bv = *(const uint2*)&Bk[(n0w + nt * 8 + gid) * BPc + ko];
            b[nt][0] = bv.x;
            b[nt][1] = bv.y;
        }
#pragma unroll
        for (int mt = 0; mt < 2; mt++)
#pragma unroll
            for (int nt = 0; nt < 4; nt++)
                asm volatile(
                    "mma.sync.aligned.m16n8k16.row.col.f32.f16.f16.f32 "
                    "{%0,%1,%2,%3}, {%4,%5,%6,%7}, {%8,%9}, {%0,%1,%2,%3};"
                    : "+f"(d[mt][nt][0]), "+f"(d[mt][nt][1]),
                      "+f"(d[mt][nt][2]), "+f"(d[mt][nt][3])
                    : "r"(a[mt][0]), "r"(a[mt][1]), "r"(a[mt][2]), "r"(a[mt][3]),
                      "r"(b[nt][0]), "r"(b[nt][1]));
    }
}

__device__ __forceinline__ float fast_sigmoid(float x) {
    return 1.0f / (1.0f + __expf(-x));
}
__device__ __forceinline__ float fast_tanh(float x) {
    x = fminf(fmaxf(x, -9.0f), 9.0f);
    float e2 = __expf(2.0f * x);
    return (e2 - 1.0f) / (e2 + 1.0f);
}

// ---------------------------------------------------------------------------
// x convert: g_xt[grp][t][m][c] = fp16(x[grp*64+m, t, kinv16(c)]) (0 if k>=65)
// ---------------------------------------------------------------------------
__global__ void __launch_bounds__(128)
xt_kernel(const float* __restrict__ inputs) {
    const int t = blockIdx.x;
    const int grp = blockIdx.y;
    __half* dst = g_xt + ((size_t)grp * TT + t) * (64 * APH);
    const float* src = inputs + (size_t)grp * 64 * (TT * 65) + (size_t)t * 65;
    for (int idx = threadIdx.x; idx < 64 * APH; idx += 128) {
        int m = idx / APH, c = idx - m * APH;
        int k = (c & ~15) + kinv16(c & 15);
        float v = (c < 80 && k < 65) ? src[(size_t)m * (TT * 65) + k] : 0.0f;
        dst[idx] = __float2half_rn(v);
    }
}

// ---------------------------------------------------------------------------
// Persistent fp16 mma.sync LSTM recurrence. Warps 0-7 compute (split-K 2x2x2),
// warp 8 = sequencer publishing per-chunk readiness to SMEM. Ep buffers
// dedicated (no A aliasing). Flags/gating as in R15.
// ---------------------------------------------------------------------------
__global__ void __launch_bounds__(RTHREADS, 1)
lstm_mma(const float* __restrict__ W_ih, const float* __restrict__ W_hh,
         const float* __restrict__ b_ih, const float* __restrict__ b_hh) {
    extern __shared__ __align__(16) char sm[];
    __half* Whh = (__half*)(sm + OFF_WHH);
    __half* Wih = (__half*)(sm + OFF_WIH);
    __half* A0 = (__half*)(sm + OFF_A0);
    __half* A1 = (__half*)(sm + OFF_A1);
    __half* AX = (__half*)(sm + OFF_AX);
    float* Ep0 = (float*)(sm + OFF_EP0);
    float* Ep1 = (float*)(sm + OFF_EP1);
    float* sBias = (float*)(sm + OFF_BIAS);
    unsigned* sCtrl = (unsigned*)(sm + OFF_CTRL);

    const int tid = threadIdx.x;
    const int lane = tid & 31;
    const int wid = tid >> 5;
    const int gid = lane >> 2, tig = lane & 3;
    const int kh = (wid >> 2) & 1;
    const int wq = wid & 3;
    const int m0w = (wq >> 1) * 32, n0w = (wq & 1) * 32;

    const int grp = blockIdx.x >> 5;
    const int hj = blockIdx.x & 31;
    const int batch_base = grp * 64;
    const int hid_base = hj * 16;

    unsigned* flags = (unsigned*)g_flag[grp];
    const __half* xt_base = g_xt + (size_t)grp * TT * (64 * APH);
    const uint32_t sProgA = smaddr(&sCtrl[0]);

    // ---- one-time: weights (fp16, k16-permuted) + bias ----
    for (int idx = tid; idx < 64 * BPH; idx += RTHREADS) {
        int r = idx / BPH, c = idx - r * BPH;
        int u = r >> 2, g = r & 3;
        int grow = g * KH + hid_base + u;
        float w = 0.0f;
        if (c < KH) {
            int k = (c & ~15) + kinv16(c & 15);
            w = W_hh[(size_t)grow * KH + k];
        }
        Whh[idx] = __float2half_rn(w);
    }
    for (int idx = tid; idx < 64 * XWPH; idx += RTHREADS) {
        int r = idx / XWPH, c = idx - r * XWPH;
        int u = r >> 2, g = r & 3;
        int grow = g * KH + hid_base + u;
        float w = 0.0f;
        if (c < 80) {
            int k = (c & ~15) + kinv16(c & 15);
            if (k < 65) w = W_ih[(size_t)grow * 65 + k];
        }
        Wih[idx] = __float2half_rn(w);
    }
    for (int idx = tid; idx < 64; idx += RTHREADS) {
        int u = idx >> 2, g = idx & 3;
        int grow = g * KH + hid_base + u;
        sBias[idx] = b_ih[grow] + b_hh[grow];
    }
    if (tid == 0) {
        sCtrl[0] = 8u;
        sCtrl[1] = ld_acq(&flags[hj * 32]);
    }
    if (tid < CTH) prefetch_ax(xt_base, AX, tid);
    __syncthreads();

    const unsigned base = sCtrl[1];

    // ================= sequencer warp =================
    if (tid >= CTH) {
        const unsigned* fp = (const unsigned*)flags + lane * 32;
        for (int t = 1; t < TT; t++) {
            const unsigned tgt = base + (unsigned)t;
            int j = 0;
            while (j < 8) {
                unsigned v = ld_acq(fp);
                unsigned m = __ballot_sync(0xFFFFFFFFu, (int)(v - tgt) >= 0);
                int nj = j;
                while (nj < 8 && ((m >> (4 * nj)) & 0xFu) == 0xFu) nj++;
                if (nj > j) {
                    j = nj;
                    if (lane == 0) st_rel_sh(sProgA, (unsigned)(t * 8 + j));
                }
            }
        }
        return;
    }

    // ================= compute warps =================
    const int mcell = tid >> 2;
    const int qu = tid & 3;              // owns units {2qu, 2qu+1, 2qu+8, 2qu+9}
    float c_state[4];
#pragma unroll
    for (int i = 0; i < 4; i++) c_state[i] = 0.0f;

    for (int t = 0; t < TT; ++t) {
        float d[2][4][4];
#pragma unroll
        for (int mt = 0; mt < 2; mt++)
#pragma unroll
            for (int nt = 0; nt < 4; nt++)
#pragma unroll
                for (int i = 0; i < 4; i++) d[mt][nt][i] = 0.0f;

        if (t > 0) {
            const unsigned pt = (unsigned)(t * 8);
            gate(sProgA, pt + 1);

            const __half* src = g_hs + (size_t)(t - 1) * BB * KH +
                                (size_t)batch_base * KH;
            prefetch_h(src, A0, 0, tid);
            CP_WAIT1();                  // AX(t) arrived; chunk0 in flight
            BAR1();

            if (kh == 0)
                compute_chunk<0, 3, APH, XWPH>(AX, Wih, m0w, n0w, gid, tig, d);
            else
                compute_chunk<3, 5, APH, XWPH>(AX, Wih, m0w, n0w, gid, tig, d);

#pragma unroll 1
            for (int j = 0; j < 8; j++) {
                CP_WAIT0();
                BAR1();
                if (j < 7) {
                    gate(sProgA, pt + (unsigned)(j + 2));
                    prefetch_h(src, (j & 1) ? A0 : A1, j + 1, tid);
                }
                const __half* Ab = (j & 1) ? A1 : A0;
                if (kh == 0)
                    compute_chunk<0, 2, APH, BPH>(Ab, Whh + j * 64, m0w, n0w,
                                                  gid, tig, d);
                else
                    compute_chunk<2, 4, APH, BPH>(Ab, Whh + j * 64, m0w, n0w,
                                                  gid, tig, d);
            }
        } else {
            CP_WAIT0();                  // AX(0)
            BAR1();
            if (kh == 0)
                compute_chunk<0, 3, APH, XWPH>(AX, Wih, m0w, n0w, gid, tig, d);
            else
                compute_chunk<3, 5, APH, XWPH>(AX, Wih, m0w, n0w, gid, tig, d);
        }

        // ---- fragments -> dedicated Ep (no aliasing; prev reads fenced) ----
        float* Ep = kh ? Ep1 : Ep0;
#pragma unroll
        for (int mt = 0; mt < 2; mt++)
#pragma unroll
            for (int nt = 0; nt < 4; nt++) {
                int rrow = m0w + mt * 16 + gid;
                int col = n0w + nt * 8 + tig * 2;
                Ep[rrow * EPITCH + col] = d[mt][nt][0];
                Ep[rrow * EPITCH + col + 1] = d[mt][nt][1];
                Ep[(rrow + 8) * EPITCH + col] = d[mt][nt][2];
                Ep[(rrow + 8) * EPITCH + col + 1] = d[mt][nt][3];
            }
        BAR1();

        // ---- cell for units {2qu,2qu+1,2qu+8,2qu+9}; permuted 8B h store ----
        {
            __half* hdst = g_hs + (size_t)t * BB * KH +
                           (size_t)(batch_base + mcell) * KH + hid_base;
            float hv[4];
#pragma unroll
            for (int i = 0; i < 4; i++) {
                int u = 2 * qu + (i & 1) + ((i >> 1) << 3);
                float4 gA = *(const float4*)&Ep0[mcell * EPITCH + 4 * u];
                float4 gB = *(const float4*)&Ep1[mcell * EPITCH + 4 * u];
                float4 bb = *(const float4*)&sBias[4 * u];
                float iv = fast_sigmoid(gA.x + gB.x + bb.x);
                float fv = fast_sigmoid(gA.y + gB.y + bb.y);
                float gv = fast_tanh(gA.z + gB.z + bb.z);
                float ov = fast_sigmoid(gA.w + gB.w + bb.w);
                float cc = fv * c_state[i] + iv * gv;
                c_state[i] = cc;
                hv[i] = ov * fast_tanh(cc);
            }
            // slots p16: units (2qu,2qu+1,2qu+8,2qu+9) -> 4qu..4qu+3
            __half2 lo = __floats2half2_rn(hv[0], hv[1]);
            __half2 hi = __floats2half2_rn(hv[2], hv[3]);
            uint2 pk;
            pk.x = *(uint32_t*)&lo;
            pk.y = *(uint32_t*)&hi;
            *(uint2*)(hdst + 4 * qu) = pk;
        }
        BAR1();   // Ep reads + h stores done before release / AX refill

        if (tid == 0) {
            st_rel(&flags[hj * 32], base + (unsigned)t + 1u);
        }
        if (t + 1 < TT)
            prefetch_ax(xt_base + (size_t)(t + 1) * (64 * APH), AX, tid);
    }
}

// ---------------------------------------------------------------------------
// Output projection: out[b,t,:] = hs[t,b,:] @ V_w^T + V_b
// (h rows fp16 + k16-permuted; V_w rows permuted identically -> identity)
// ---------------------------------------------------------------------------
#define NTHREADS 256
#define PROJ_ROWS 64
#define PROJ_CHUNK 16
#define VPAD 68

__global__ void __launch_bounds__(NTHREADS, 1)
proj_kernel(const float* __restrict__ V_w, const float* __restrict__ V_b,
            float* __restrict__ out) {
    extern __shared__ __align__(16) char smc[];
    float* sV = (float*)smc;                          // [512][VPAD]
    __half* sHr = (__half*)(smc + KH * VPAD * 4);     // [16][512] half
    float* sVb = (float*)(smc + KH * VPAD * 4 + PROJ_CHUNK * KH * 2);

    const int tid = threadIdx.x;
    const int mg = tid & 15;
    const int rs = tid >> 4;

    for (int idx = tid; idx < MM * KH; idx += NTHREADS) {
        int m = idx >> 9;
        int k = idx & 511;
        int slot = (k & ~15) + p16(k & 15);
        sV[slot * VPAD + m] = V_w[idx];
    }
    for (int idx = tid; idx < MM; idx += NTHREADS) sVb[idx] = V_b[idx];
    __syncthreads();

    const int row_base = blockIdx.x * PROJ_ROWS;

    for (int ch = 0; ch < PROJ_ROWS; ch += PROJ_CHUNK) {
        const float4* src = (const float4*)(g_hs + (size_t)(row_base + ch) * KH);
        for (int idx = tid; idx < PROJ_CHUNK * (KH / 8); idx += NTHREADS) {
            ((float4*)sHr)[idx] = src[idx];    // 512 halves = 64 float4 per row
        }
        __syncthreads();

        float acc0 = sVb[mg * 4 + 0];
        float acc1 = sVb[mg * 4 + 1];
        float acc2 = sVb[mg * 4 + 2];
        float acc3 = sVb[mg * 4 + 3];
        const __half2* hr = (const __half2*)(sHr + rs * KH);
#pragma unroll 4
        for (int q = 0; q < KH / 2; q++) {
            float2 hf = __half22float2(hr[q]);
            const float* v0 = &sV[(2 * q) * VPAD + mg * 4];
            const float* v1 = &sV[(2 * q + 1) * VPAD + mg * 4];
            float4 a = *(const float4*)v0;
            float4 b = *(const float4*)v1;
            acc0 += hf.x * a.x + hf.y * b.x;
            acc1 += hf.x * a.y + hf.y * b.y;
            acc2 += hf.x * a.z + hf.y * b.z;
            acc3 += hf.x * a.w + hf.y * b.w;
        }

        int row = row_base + ch + rs;   // linear = t*B + b
        int t = row >> 8;
        int b = row & 255;
        float4 o = make_float4(acc0, acc1, acc2, acc3);
        *(float4*)&out[((size_t)b * TT + t) * MM + mg * 4] = o;
        __syncthreads();
    }
}

extern "C" void kernel_launch(void* const* d_in, const int* in_sizes, int n_in,
                              void* d_out, int out_size) {
    const float* inputs = (const float*)d_in[0];
    const float* W_ih   = (const float*)d_in[1];
    const float* W_hh   = (const float*)d_in[2];
    const float* b_ih   = (const float*)d_in[3];
    const float* b_hh   = (const float*)d_in[4];
    const float* V_w    = (const float*)d_in[5];
    const float* V_b    = (const float*)d_in[6];
    float* out = (float*)d_out;

    const int smem2 = KH * VPAD * 4 + PROJ_CHUNK * KH * 2 + 64 * 4 + 16;

    cudaFuncSetAttribute(lstm_mma, cudaFuncAttributeMaxDynamicSharedMemorySize,
                         SMEM_BYTES);
    cudaFuncSetAttribute(proj_kernel, cudaFuncAttributeMaxDynamicSharedMemorySize,
                         smem2);

    xt_kernel<<<dim3(TT, 4), 128>>>(inputs);
    lstm_mma<<<NCTA_R, RTHREADS, SMEM_BYTES>>>(W_ih, W_hh, b_ih, b_hh);
    proj_kernel<<<(BB * TT) / PROJ_ROWS, NTHREADS, smem2>>>(V_w, V_b, out);
}

// round 17
// speedup vs baseline: 1.4463x; 1.0128x over previous
#include <cuda_runtime.h>
#include <cuda_fp16.h>
#include <math.h>
#include <stdint.h>

#define BB 256
#define TT 1024
#define MM 64
#define KH 512

#define RTHREADS 288          // 8 compute warps + 1 sequencer warp
#define CTH 256
#define NCTA_R 128
#define GRP_CTAS 32

#define HPH 136               // h-chunk pitch halves (272B; 68%32=4 -> conflict-free)
#define XPH 88                // x tile pitch halves (176B; 44%32=12 -> conflict-free)
#define BPH 524               // Whh pitch halves (262%32=6 -> conflict-free)
#define XWPH 84               // Wih pitch halves (42%32=10 -> conflict-free)
#define EPITCH 68             // epilogue float pitch

// byte offsets into dynamic SMEM (all 16B aligned)
#define OFF_WHH 0
#define OFF_WIH (64 * BPH * 2)                 // 67072
#define OFF_A0 (OFF_WIH + 64 * XWPH * 2)       // 77824
#define OFF_A1 (OFF_A0 + 64 * HPH * 2)         // 95232
#define OFF_AX (OFF_A1 + 64 * HPH * 2)         // 112640
#define OFF_EP0 (OFF_AX + 64 * XPH * 2)        // 123904
#define OFF_EP1 (OFF_EP0 + 64 * EPITCH * 4)    // 141312
#define OFF_BIAS (OFF_EP1 + 64 * EPITCH * 4)   // 158720
#define OFF_CTRL (OFF_BIAS + 64 * 4)           // 158976
#define SMEM_BYTES (OFF_CTRL + 16)             // 158992

__device__ __half g_hs[(size_t)TT * BB * KH];          // k16-permuted fp16 h history
__device__ __half g_xt[(size_t)4 * TT * 64 * XPH];     // permuted fp16 x tiles
__device__ unsigned g_flag[4][GRP_CTAS * 32];          // per-CTA flags, 128B apart

// k16 permutation: within each 16-group, order [0,1,8,9, 2,3,10,11, ...]
__device__ __host__ __forceinline__ int p16(int u) {
    return (u & 1) + (((u >> 3) & 1) << 1) + (((u >> 1) & 3) << 2);
}
__device__ __forceinline__ int kinv16(int c) {
    return (c & 1) + (((c >> 2) & 3) << 1) + (((c >> 1) & 1) << 3);
}

__device__ __forceinline__ uint32_t smaddr(const void* p) {
    return (uint32_t)__cvta_generic_to_shared(p);
}
__device__ __forceinline__ unsigned ld_acq(const unsigned* p) {
    unsigned v;
    asm volatile("ld.acquire.gpu.global.u32 %0, [%1];" : "=r"(v) : "l"(p) : "memory");
    return v;
}
__device__ __forceinline__ void st_rel(unsigned* p, unsigned v) {
    asm volatile("st.release.gpu.global.u32 [%0], %1;" :: "l"(p), "r"(v) : "memory");
}
__device__ __forceinline__ unsigned ld_acq_sh(uint32_t a) {
    unsigned v;
    asm volatile("ld.acquire.cta.shared.u32 %0, [%1];" : "=r"(v) : "r"(a) : "memory");
    return v;
}
__device__ __forceinline__ void st_rel_sh(uint32_t a, unsigned v) {
    asm volatile("st.release.cta.shared.u32 [%0], %1;" :: "r"(a), "r"(v) : "memory");
}

#define CP_COMMIT() asm volatile("cp.async.commit_group;" ::: "memory")
#define CP_WAIT0() asm volatile("cp.async.wait_group 0;" ::: "memory")
#define CP_WAIT1() asm volatile("cp.async.wait_group 1;" ::: "memory")
#define BAR1() asm volatile("bar.sync 1, 256;" ::: "memory")

__device__ __forceinline__ void gate(uint32_t sProgA, unsigned target) {
    while ((int)(ld_acq_sh(sProgA) - target) < 0) {}
}

// prefetch h chunk j (64 rows x 128 halves = 16KB) from g_hs into Ab (pitch HPH)
__device__ __forceinline__ void prefetch_h(const __half* __restrict__ srcH,
                                           __half* Ab, int j, int tid) {
    const float4* src = (const float4*)srcH;   // row stride 512h = 64 float4
#pragma unroll
    for (int i = 0; i < 4; i++) {
        int idx = tid + i * CTH;               // < 1024
        int m = idx >> 4, q = idx & 15;
        uint32_t dst = smaddr(Ab + m * HPH + q * 8);
        const float4* g = src + (size_t)m * 64 + j * 16 + q;
        asm volatile("cp.async.cg.shared.global [%0], [%1], 16;"
                     :: "r"(dst), "l"(g) : "memory");
    }
    CP_COMMIT();
}

// prefetch x tile (64 x 88 halves contiguous = 11KB) into AX
__device__ __forceinline__ void prefetch_ax(const __half* __restrict__ srcH,
                                            __half* AX, int tid) {
    const float4* src = (const float4*)srcH;
#pragma unroll
    for (int i = 0; i < 3; i++) {
        int idx = tid + i * CTH;
        if (idx < 704) {                       // 64 rows x 11 float4
            int m = idx / 11, q = idx - m * 11;
            uint32_t dst = smaddr(AX + m * XPH + q * 8);
            asm volatile("cp.async.cg.shared.global [%0], [%1], 16;"
                         :: "r"(dst), "l"(src + idx) : "memory");
        }
    }
    CP_COMMIT();
}

// fp16 m16n8k16: k16-steps [KS0,KS1). Operands k16-permuted -> LDS.64 fragments.
template <int KS0, int KS1, int APc, int BPc>
__device__ __forceinline__ void compute_chunk(const __half* __restrict__ As,
                                              const __half* __restrict__ Bk,
                                              int m0w, int n0w, int gid, int tig,
                                              float (&d)[2][4][4]) {
#pragma unroll
    for (int ks = KS0; ks < KS1; ks++) {
        const int ko = ks * 16 + 4 * tig;
        uint32_t a[2][4];
#pragma unroll
        for (int mt = 0; mt < 2; mt++) {
            uint2 lo = *(const uint2*)&As[(m0w + mt * 16 + gid) * APc + ko];
            uint2 hi = *(const uint2*)&As[(m0w + mt * 16 + 8 + gid) * APc + ko];
            a[mt][0] = lo.x;
            a[mt][1] = hi.x;
            a[mt][2] = lo.y;
            a[mt][3] = hi.y;
        }
        uint32_t b[4][2];
#pragma unroll
        for (int nt = 0; nt < 4; nt++) {
            uint2 bv = *(const uint2*)&Bk[(n0w + nt * 8 + gid) * BPc + ko];
            b[nt][0] = bv.x;
            b[nt][1] = bv.y;
        }
#pragma unroll
        for (int mt = 0; mt < 2; mt++)
#pragma unroll
            for (int nt = 0; nt < 4; nt++)
                asm volatile(
                    "mma.sync.aligned.m16n8k16.row.col.f32.f16.f16.f32 "
                    "{%0,%1,%2,%3}, {%4,%5,%6,%7}, {%8,%9}, {%0,%1,%2,%3};"
                    : "+f"(d[mt][nt][0]), "+f"(d[mt][nt][1]),
                      "+f"(d[mt][nt][2]), "+f"(d[mt][nt][3])
                    : "r"(a[mt][0]), "r"(a[mt][1]), "r"(a[mt][2]), "r"(a[mt][3]),
                      "r"(b[nt][0]), "r"(b[nt][1]));
    }
}

__device__ __forceinline__ float fast_sigmoid(float x) {
    return 1.0f / (1.0f + __expf(-x));
}
__device__ __forceinline__ float fast_tanh(float x) {
    x = fminf(fmaxf(x, -9.0f), 9.0f);
    float e2 = __expf(2.0f * x);
    return (e2 - 1.0f) / (e2 + 1.0f);
}

// ---------------------------------------------------------------------------
// x convert: g_xt[grp][t][m][c] = fp16(x[grp*64+m, t, kinv16(c)]) (0 pad)
// ---------------------------------------------------------------------------
__global__ void __launch_bounds__(128)
xt_kernel(const float* __restrict__ inputs) {
    const int t = blockIdx.x;
    const int grp = blockIdx.y;
    __half* dst = g_xt + ((size_t)grp * TT + t) * (64 * XPH);
    const float* src = inputs + (size_t)grp * 64 * (TT * 65) + (size_t)t * 65;
    for (int idx = threadIdx.x; idx < 64 * XPH; idx += 128) {
        int m = idx / XPH, c = idx - m * XPH;
        int k = (c & ~15) + kinv16(c & 15);
        float v = (c < 80 && k < 65) ? src[(size_t)m * (TT * 65) + k] : 0.0f;
        dst[idx] = __float2half_rn(v);
    }
}

// ---------------------------------------------------------------------------
// Persistent fp16 mma.sync LSTM recurrence. Warps 0-7 compute (split-K 2x2x2),
// warp 8 sequencer. 4 K=128 h-chunks per step (halved segment count); chunk j
// ready when CTAs 8j..8j+7 of the group reach step t.
// ---------------------------------------------------------------------------
__global__ void __launch_bounds__(RTHREADS, 1)
lstm_mma(const float* __restrict__ W_ih, const float* __restrict__ W_hh,
         const float* __restrict__ b_ih, const float* __restrict__ b_hh) {
    extern __shared__ __align__(16) char sm[];
    __half* Whh = (__half*)(sm + OFF_WHH);
    __half* Wih = (__half*)(sm + OFF_WIH);
    __half* A0 = (__half*)(sm + OFF_A0);
    __half* A1 = (__half*)(sm + OFF_A1);
    __half* AX = (__half*)(sm + OFF_AX);
    float* Ep0 = (float*)(sm + OFF_EP0);
    float* Ep1 = (float*)(sm + OFF_EP1);
    float* sBias = (float*)(sm + OFF_BIAS);
    unsigned* sCtrl = (unsigned*)(sm + OFF_CTRL);

    const int tid = threadIdx.x;
    const int lane = tid & 31;
    const int wid = tid >> 5;
    const int gid = lane >> 2, tig = lane & 3;
    const int kh = (wid >> 2) & 1;
    const int wq = wid & 3;
    const int m0w = (wq >> 1) * 32, n0w = (wq & 1) * 32;

    const int grp = blockIdx.x >> 5;
    const int hj = blockIdx.x & 31;
    const int batch_base = grp * 64;
    const int hid_base = hj * 16;

    unsigned* flags = (unsigned*)g_flag[grp];
    const __half* xt_base = g_xt + (size_t)grp * TT * (64 * XPH);
    const uint32_t sProgA = smaddr(&sCtrl[0]);

    // ---- one-time: weights (fp16, k16-permuted) + bias ----
    for (int idx = tid; idx < 64 * BPH; idx += RTHREADS) {
        int r = idx / BPH, c = idx - r * BPH;
        int u = r >> 2, g = r & 3;
        int grow = g * KH + hid_base + u;
        float w = 0.0f;
        if (c < KH) {
            int k = (c & ~15) + kinv16(c & 15);
            w = W_hh[(size_t)grow * KH + k];
        }
        Whh[idx] = __float2half_rn(w);
    }
    for (int idx = tid; idx < 64 * XWPH; idx += RTHREADS) {
        int r = idx / XWPH, c = idx - r * XWPH;
        int u = r >> 2, g = r & 3;
        int grow = g * KH + hid_base + u;
        float w = 0.0f;
        if (c < 80) {
            int k = (c & ~15) + kinv16(c & 15);
            if (k < 65) w = W_ih[(size_t)grow * 65 + k];
        }
        Wih[idx] = __float2half_rn(w);
    }
    for (int idx = tid; idx < 64; idx += RTHREADS) {
        int u = idx >> 2, g = idx & 3;
        int grow = g * KH + hid_base + u;
        sBias[idx] = b_ih[grow] + b_hh[grow];
    }
    if (tid == 0) {
        sCtrl[0] = 4u;                          // below first target (t*4+1 = 5)
        sCtrl[1] = ld_acq(&flags[hj * 32]);     // replay-safe base
    }
    if (tid < CTH) prefetch_ax(xt_base, AX, tid);
    __syncthreads();

    const unsigned base = sCtrl[1];

    // ================= sequencer warp =================
    if (tid >= CTH) {
        const unsigned* fp = (const unsigned*)flags + lane * 32;
        for (int t = 1; t < TT; t++) {
            const unsigned tgt = base + (unsigned)t;
            int j = 0;
            while (j < 4) {
                unsigned v = ld_acq(fp);
                unsigned m = __ballot_sync(0xFFFFFFFFu, (int)(v - tgt) >= 0);
                int nj = j;
                while (nj < 4 && ((m >> (8 * nj)) & 0xFFu) == 0xFFu) nj++;
                if (nj > j) {
                    j = nj;
                    if (lane == 0) st_rel_sh(sProgA, (unsigned)(t * 4 + j));
                }
            }
        }
        return;
    }

    // ================= compute warps =================
    const int mcell = tid >> 2;
    const int qu = tid & 3;              // owns units {2qu, 2qu+1, 2qu+8, 2qu+9}
    float c_state[4];
#pragma unroll
    for (int i = 0; i < 4; i++) c_state[i] = 0.0f;

    for (int t = 0; t < TT; ++t) {
        float d[2][4][4];
#pragma unroll
        for (int mt = 0; mt < 2; mt++)
#pragma unroll
            for (int nt = 0; nt < 4; nt++)
#pragma unroll
                for (int i = 0; i < 4; i++) d[mt][nt][i] = 0.0f;

        if (t > 0) {
            const unsigned pt = (unsigned)(t * 4);
            gate(sProgA, pt + 1);        // chunk0 producers (CTAs 0..7)

            const __half* src = g_hs + (size_t)(t - 1) * BB * KH +
                                (size_t)batch_base * KH;
            prefetch_h(src, A0, 0, tid);
            CP_WAIT1();                  // AX(t) arrived; chunk0 in flight
            BAR1();

            if (kh == 0)
                compute_chunk<0, 3, XPH, XWPH>(AX, Wih, m0w, n0w, gid, tig, d);
            else
                compute_chunk<3, 5, XPH, XWPH>(AX, Wih, m0w, n0w, gid, tig, d);

#pragma unroll 1
            for (int j = 0; j < 4; j++) {
                CP_WAIT0();
                BAR1();
                if (j < 3) {
                    gate(sProgA, pt + (unsigned)(j + 2));
                    prefetch_h(src, (j & 1) ? A0 : A1, j + 1, tid);
                }
                const __half* Ab = (j & 1) ? A1 : A0;
                if (kh == 0)
                    compute_chunk<0, 4, HPH, BPH>(Ab, Whh + j * 128, m0w, n0w,
                                                  gid, tig, d);
                else
                    compute_chunk<4, 8, HPH, BPH>(Ab, Whh + j * 128, m0w, n0w,
                                                  gid, tig, d);
            }
        } else {
            CP_WAIT0();                  // AX(0)
            BAR1();
            if (kh == 0)
                compute_chunk<0, 3, XPH, XWPH>(AX, Wih, m0w, n0w, gid, tig, d);
            else
                compute_chunk<3, 5, XPH, XWPH>(AX, Wih, m0w, n0w, gid, tig, d);
        }

        // ---- fragments -> dedicated Ep buffers ----
        float* Ep = kh ? Ep1 : Ep0;
#pragma unroll
        for (int mt = 0; mt < 2; mt++)
#pragma unroll
            for (int nt = 0; nt < 4; nt++) {
                int rrow = m0w + mt * 16 + gid;
                int col = n0w + nt * 8 + tig * 2;
                Ep[rrow * EPITCH + col] = d[mt][nt][0];
                Ep[rrow * EPITCH + col + 1] = d[mt][nt][1];
                Ep[(rrow + 8) * EPITCH + col] = d[mt][nt][2];
                Ep[(rrow + 8) * EPITCH + col + 1] = d[mt][nt][3];
            }
        BAR1();

        // ---- cell for units {2qu,2qu+1,2qu+8,2qu+9}; permuted 8B h store ----
        {
            __half* hdst = g_hs + (size_t)t * BB * KH +
                           (size_t)(batch_base + mcell) * KH + hid_base;
            float hv[4];
#pragma unroll
            for (int i = 0; i < 4; i++) {
                int u = 2 * qu + (i & 1) + ((i >> 1) << 3);
                float4 gA = *(const float4*)&Ep0[mcell * EPITCH + 4 * u];
                float4 gB = *(const float4*)&Ep1[mcell * EPITCH + 4 * u];
                float4 bb = *(const float4*)&sBias[4 * u];
                float iv = fast_sigmoid(gA.x + gB.x + bb.x);
                float fv = fast_sigmoid(gA.y + gB.y + bb.y);
                float gv = fast_tanh(gA.z + gB.z + bb.z);
                float ov = fast_sigmoid(gA.w + gB.w + bb.w);
                float cc = fv * c_state[i] + iv * gv;
                c_state[i] = cc;
                hv[i] = ov * fast_tanh(cc);
            }
            __half2 lo = __floats2half2_rn(hv[0], hv[1]);
            __half2 hi = __floats2half2_rn(hv[2], hv[3]);
            uint2 pk;
            pk.x = *(uint32_t*)&lo;
            pk.y = *(uint32_t*)&hi;
            *(uint2*)(hdst + 4 * qu) = pk;
        }
        BAR1();   // Ep reads + h stores done before release / AX refill

        if (tid == 0) {
            st_rel(&flags[hj * 32], base + (unsigned)t + 1u);
        }
        if (t + 1 < TT)
            prefetch_ax(xt_base + (size_t)(t + 1) * (64 * XPH), AX, tid);
    }
}

// ---------------------------------------------------------------------------
// Output projection: out[b,t,:] = hs[t,b,:] @ V_w^T + V_b
// (h rows fp16 + k16-permuted; V_w rows permuted identically -> identity)
// ---------------------------------------------------------------------------
#define NTHREADS 256
#define PROJ_ROWS 64
#define PROJ_CHUNK 16
#define VPAD 68

__global__ void __launch_bounds__(NTHREADS, 1)
proj_kernel(const float* __restrict__ V_w, const float* __restrict__ V_b,
            float* __restrict__ out) {
    extern __shared__ __align__(16) char smc[];
    float* sV = (float*)smc;                          // [512][VPAD]
    __half* sHr = (__half*)(smc + KH * VPAD * 4);     // [16][512] half
    float* sVb = (float*)(smc + KH * VPAD * 4 + PROJ_CHUNK * KH * 2);

    const int tid = threadIdx.x;
    const int mg = tid & 15;
    const int rs = tid >> 4;

    for (int idx = tid; idx < MM * KH; idx += NTHREADS) {
        int m = idx >> 9;
        int k = idx & 511;
        int slot = (k & ~15) + p16(k & 15);
        sV[slot * VPAD + m] = V_w[idx];
    }
    for (int idx = tid; idx < MM; idx += NTHREADS) sVb[idx] = V_b[idx];
    __syncthreads();

    const int row_base = blockIdx.x * PROJ_ROWS;

    for (int ch = 0; ch < PROJ_ROWS; ch += PROJ_CHUNK) {
        const float4* src = (const float4*)(g_hs + (size_t)(row_base + ch) * KH);
        for (int idx = tid; idx < PROJ_CHUNK * (KH / 8); idx += NTHREADS) {
            ((float4*)sHr)[idx] = src[idx];
        }
        __syncthreads();

        float acc0 = sVb[mg * 4 + 0];
        float acc1 = sVb[mg * 4 + 1];
        float acc2 = sVb[mg * 4 + 2];
        float acc3 = sVb[mg * 4 + 3];
        const __half2* hr = (const __half2*)(sHr + rs * KH);
#pragma unroll 4
        for (int q = 0; q < KH / 2; q++) {
            float2 hf = __half22float2(hr[q]);
            float4 a = *(const float4*)&sV[(2 * q) * VPAD + mg * 4];
            float4 b = *(const float4*)&sV[(2 * q + 1) * VPAD + mg * 4];
            acc0 += hf.x * a.x + hf.y * b.x;
            acc1 += hf.x * a.y + hf.y * b.y;
            acc2 += hf.x * a.z + hf.y * b.z;
            acc3 += hf.x * a.w + hf.y * b.w;
        }

        int row = row_base + ch + rs;   // linear = t*B + b
        int t = row >> 8;
        int b = row & 255;
        float4 o = make_float4(acc0, acc1, acc2, acc3);
        *(float4*)&out[((size_t)b * TT + t) * MM + mg * 4] = o;
        __syncthreads();
    }
}

extern "C" void kernel_launch(void* const* d_in, const int* in_sizes, int n_in,
                              void* d_out, int out_size) {
    const float* inputs = (const float*)d_in[0];
    const float* W_ih   = (const float*)d_in[1];
    const float* W_hh   = (const float*)d_in[2];
    const float* b_ih   = (const float*)d_in[3];
    const float* b_hh   = (const float*)d_in[4];
    const float* V_w    = (const float*)d_in[5];
    const float* V_b    = (const float*)d_in[6];
    float* out = (float*)d_out;

    const int smem2 = KH * VPAD * 4 + PROJ_CHUNK * KH * 2 + 64 * 4 + 16;

    cudaFuncSetAttribute(lstm_mma, cudaFuncAttributeMaxDynamicSharedMemorySize,
                         SMEM_BYTES);
    cudaFuncSetAttribute(proj_kernel, cudaFuncAttributeMaxDynamicSharedMemorySize,
                         smem2);

    xt_kernel<<<dim3(TT, 4), 128>>>(inputs);
    lstm_mma<<<NCTA_R, RTHREADS, SMEM_BYTES>>>(W_ih, W_hh, b_ih, b_hh);
    proj_kernel<<<(BB * TT) / PROJ_ROWS, NTHREADS, smem2>>>(V_w, V_b, out);
}